// round 13
// baseline (speedup 1.0000x reference)
#include <cuda_runtime.h>

#define MN 50000      // nodes
#define EN 800000     // edges
#define FIN 32
#define NB 4
#define KORD 4
#define CH 32
#define ROWLEN 128    // NB*FIN floats per node row
#define CAP 80        // bucket capacity per row (Poisson mean 16; P(>80) ~ 0)
#define GTHR 128      // gemm threads per block == rows per block (1 row/thread)
#define TSTRIDE 36    // smem row stride (floats): 16B aligned + conflict-free

// ---------------- device scratch (static, no allocations) ----------------
__device__ float  d_T1[MN * ROWLEN];
__device__ float  d_T2[MN * ROWLEN];
__device__ float  d_T3[MN * ROWLEN];
__device__ float2 d_ev[MN * CAP];    // {val, col-as-bits} bucketed per row
__device__ int    d_cnt[MN];         // zero-init at load; re-zeroed by gemm tail

// ---------------- bucket scatter ----------------
__global__ void scatter_k(const float* __restrict__ vals,
                          const int* __restrict__ rows,
                          const int* __restrict__ cols) {
    int i = blockIdx.x * blockDim.x + threadIdx.x;   // 4 edges per thread
    if (i * 4 < EN) {
        int4   r = *(const int4*)(rows + i * 4);
        int4   c = *(const int4*)(cols + i * 4);
        float4 v = *(const float4*)(vals + i * 4);
        int s0 = atomicAdd(&d_cnt[r.x], 1);
        int s1 = atomicAdd(&d_cnt[r.y], 1);
        int s2 = atomicAdd(&d_cnt[r.z], 1);
        int s3 = atomicAdd(&d_cnt[r.w], 1);
        d_ev[r.x * CAP + s0] = make_float2(v.x, __int_as_float(c.x));
        d_ev[r.y * CAP + s1] = make_float2(v.y, __int_as_float(c.y));
        d_ev[r.z * CAP + s2] = make_float2(v.z, __int_as_float(c.z));
        d_ev[r.w * CAP + s3] = make_float2(v.w, __int_as_float(c.w));
    }
}

// ---------------- SpMM: Xout = alpha*(L @ Xin) - Xsub ----------------
// Single-line gather shape: lane j handles elements j, j+32, j+64, j+96 of each
// logical 128-float row. Every LDG.32 has all 32 lanes within ONE 128B line
// (1 wavefront @ cross-LDG rate) vs the old LDG.128 spanning 4 lines
// (4 wavefronts @ within-LDG replay rate). 16 independent loads per 4-edge group.
// Element addressing: Xin[lane + col*instride + jj*termstride]
//   T-layout (m-major rows): instride=ROWLEN, termstride=FIN
//   x-layout ([n][m][f]):    instride=FIN,    termstride=MN*FIN
template <int XIN_X, int SUB, int XSUB_X>
__global__ void __launch_bounds__(256) spmm_k(const float* __restrict__ Xin,
                                              const float* __restrict__ Xsub,
                                              float* __restrict__ Xout,
                                              float alpha) {
    int r = blockIdx.x * (blockDim.x >> 5) + (threadIdx.x >> 5);
    if (r >= MN) return;
    int lane = threadIdx.x & 31;

    const int instride   = XIN_X ? FIN : ROWLEN;
    const int termstride = XIN_X ? MN * FIN : FIN;
    const float* inb = Xin + lane;

    int cnt = __ldg(&d_cnt[r]);
    const float4* ev4 = (const float4*)(d_ev + (size_t)r * CAP);

    // prefetch subtrahend (4 single-line coalesced loads, overlap gather loop)
    float s0 = 0.f, s1 = 0.f, s2 = 0.f, s3 = 0.f;
    if (SUB) {
        const int sstride = XSUB_X ? FIN : ROWLEN;
        const int sterm   = XSUB_X ? MN * FIN : FIN;
        const float* sb = Xsub + (size_t)r * sstride + lane;
        s0 = __ldg(sb);
        s1 = __ldg(sb + sterm);
        s2 = __ldg(sb + 2 * sterm);
        s3 = __ldg(sb + 3 * sterm);
    }

    float a0 = 0.f, a1 = 0.f, a2 = 0.f, a3 = 0.f;

    int G = cnt >> 2;                 // groups of 4 edges (2 float4 ev loads)
    for (int g = 0; g < G; g++) {
        float4 p = __ldg(&ev4[2 * g]);
        float4 q = __ldg(&ev4[2 * g + 1]);
        const float* b0 = inb + (size_t)__float_as_int(p.y) * instride;
        const float* b1 = inb + (size_t)__float_as_int(p.w) * instride;
        const float* b2 = inb + (size_t)__float_as_int(q.y) * instride;
        const float* b3 = inb + (size_t)__float_as_int(q.w) * instride;
        // 16 independent single-line LDG.32s
        float x00 = __ldg(b0);                  float x01 = __ldg(b0 + termstride);
        float x02 = __ldg(b0 + 2 * termstride); float x03 = __ldg(b0 + 3 * termstride);
        float x10 = __ldg(b1);                  float x11 = __ldg(b1 + termstride);
        float x12 = __ldg(b1 + 2 * termstride); float x13 = __ldg(b1 + 3 * termstride);
        float x20 = __ldg(b2);                  float x21 = __ldg(b2 + termstride);
        float x22 = __ldg(b2 + 2 * termstride); float x23 = __ldg(b2 + 3 * termstride);
        float x30 = __ldg(b3);                  float x31 = __ldg(b3 + termstride);
        float x32 = __ldg(b3 + 2 * termstride); float x33 = __ldg(b3 + 3 * termstride);
        a0 = fmaf(p.x, x00, a0); a1 = fmaf(p.x, x01, a1);
        a2 = fmaf(p.x, x02, a2); a3 = fmaf(p.x, x03, a3);
        a0 = fmaf(p.z, x10, a0); a1 = fmaf(p.z, x11, a1);
        a2 = fmaf(p.z, x12, a2); a3 = fmaf(p.z, x13, a3);
        a0 = fmaf(q.x, x20, a0); a1 = fmaf(q.x, x21, a1);
        a2 = fmaf(q.x, x22, a2); a3 = fmaf(q.x, x23, a3);
        a0 = fmaf(q.z, x30, a0); a1 = fmaf(q.z, x31, a1);
        a2 = fmaf(q.z, x32, a2); a3 = fmaf(q.z, x33, a3);
    }
    const float2* evp = (const float2*)ev4;
    for (int e = G * 4; e < cnt; e++) {
        float2 a = __ldg(&evp[e]);
        const float* b = inb + (size_t)__float_as_int(a.y) * instride;
        float y0 = __ldg(b);                  float y1 = __ldg(b + termstride);
        float y2 = __ldg(b + 2 * termstride); float y3 = __ldg(b + 3 * termstride);
        a0 = fmaf(a.x, y0, a0); a1 = fmaf(a.x, y1, a1);
        a2 = fmaf(a.x, y2, a2); a3 = fmaf(a.x, y3, a3);
    }

    // coalesced single-line stores: element j+32*jj of the output row
    float* ob = Xout + (size_t)r * ROWLEN + lane;
    ob[0]       = fmaf(alpha, a0, -s0);
    ob[FIN]     = fmaf(alpha, a1, -s1);
    ob[2 * FIN] = fmaf(alpha, a2, -s2);
    ob[3 * FIN] = fmaf(alpha, a3, -s3);
}

// ---------------- cp.async helpers ----------------
__device__ __forceinline__ void cp16(void* smem_dst, const void* gmem_src) {
    unsigned int s = (unsigned int)__cvta_generic_to_shared(smem_dst);
    asm volatile("cp.async.cg.shared.global [%0], [%1], 16;" :: "r"(s), "l"(gmem_src));
}
__device__ __forceinline__ void cp_commit() {
    asm volatile("cp.async.commit_group;");
}
template <int N>
__device__ __forceinline__ void cp_wait() {
    asm volatile("cp.async.wait_group %0;" :: "n"(N));
}

// ---------------- fused GEMM + bias + relu (cp.async double-buffered k-pipeline) ----------------
// out[n,m,c] = relu( bias[c] + sum_{f,k} T_k[m][n*32+f] * W[f*4+k][c] )
__global__ void __launch_bounds__(GTHR) gemm_k(const float* __restrict__ x,
                                               const float* __restrict__ T1,
                                               const float* __restrict__ T2,
                                               const float* __restrict__ T3,
                                               const float* __restrict__ Wg,
                                               const float* __restrict__ bias,
                                               float* __restrict__ out) {
    __shared__ float Ts[2][GTHR * TSTRIDE];  // 2 x 18 KB row tiles
    __shared__ float Wk[2][FIN * CH];        // 2 x 4 KB per-k weights
    __shared__ float bsm[CH];

    int tid = threadIdx.x;
    if (tid < CH) bsm[tid] = __ldg(&bias[tid]);

    int base_nm = blockIdx.x * GTHR;
    int my_nm = base_nm + tid;
    // re-zero d_cnt for next call (safe: gemm runs after all spmm reads)
    if (my_nm < MN) d_cnt[my_nm] = 0;

    auto stage = [&](int k, int b) {
        const float* Tk = (k == 1) ? T1 : (k == 2) ? T2 : T3;
        #pragma unroll
        for (int ss = 0; ss < 8; ss++) {
            int row = (tid >> 3) + ss * (GTHR / 8);
            int nm = base_nm + row;
            if (nm > NB * MN - 1) nm = NB * MN - 1;
            const float* src;
            if (k == 0) {
                src = x + (size_t)nm * FIN;
            } else {
                int n = nm / MN;
                int m = nm - n * MN;
                src = Tk + m * ROWLEN + n * FIN;
            }
            cp16(Ts[b] + row * TSTRIDE + (tid & 7) * 4, src + (tid & 7) * 4);
        }
        #pragma unroll
        for (int j = 0; j < 2; j++) {
            int chunk = tid + j * GTHR;          // 0..255
            int f = chunk >> 3, c4 = chunk & 7;
            cp16(Wk[b] + f * CH + c4 * 4, Wg + (f * KORD + k) * CH + c4 * 4);
        }
    };

    unsigned long long acc2[CH / 2];             // packed f32x2 channel pairs
    #pragma unroll
    for (int i = 0; i < CH / 2; i++) acc2[i] = 0ull;

    stage(0, 0); cp_commit();

    #pragma unroll
    for (int k = 0; k < KORD; k++) {
        if (k < KORD - 1) { stage(k + 1, (k + 1) & 1); cp_commit(); }
        if (k < KORD - 1) cp_wait<1>(); else cp_wait<0>();
        __syncthreads();

        const float* myrow = Ts[k & 1] + tid * TSTRIDE;
        const float* wbase = Wk[k & 1];
        #pragma unroll
        for (int q = 0; q < 8; q++) {
            float4 xq = *(const float4*)(myrow + q * 4);
            #pragma unroll
            for (int ff = 0; ff < 4; ff++) {
                float xf = (ff == 0) ? xq.x : (ff == 1) ? xq.y : (ff == 2) ? xq.z : xq.w;
                unsigned long long xx;
                unsigned int xb = __float_as_uint(xf);
                asm("mov.b64 %0, {%1, %1};" : "=l"(xx) : "r"(xb));
                const ulonglong2* wr = (const ulonglong2*)(wbase + (q * 4 + ff) * CH);
                #pragma unroll
                for (int c8 = 0; c8 < 8; c8++) {
                    ulonglong2 w = wr[c8];
                    asm("fma.rn.f32x2 %0, %1, %2, %0;" : "+l"(acc2[c8 * 2 + 0]) : "l"(xx), "l"(w.x));
                    asm("fma.rn.f32x2 %0, %1, %2, %0;" : "+l"(acc2[c8 * 2 + 1]) : "l"(xx), "l"(w.y));
                }
            }
        }
        __syncthreads();
    }

    if (my_nm < NB * MN) {
        float* op = out + (size_t)my_nm * CH;
        #pragma unroll
        for (int c4 = 0; c4 < 8; c4++) {
            unsigned int l0, h0, l1, h1;
            asm("mov.b64 {%0, %1}, %2;" : "=r"(l0), "=r"(h0) : "l"(acc2[c4 * 2 + 0]));
            asm("mov.b64 {%0, %1}, %2;" : "=r"(l1), "=r"(h1) : "l"(acc2[c4 * 2 + 1]));
            float4 r;
            r.x = fmaxf(__uint_as_float(l0) + bsm[c4 * 4 + 0], 0.f);
            r.y = fmaxf(__uint_as_float(h0) + bsm[c4 * 4 + 1], 0.f);
            r.z = fmaxf(__uint_as_float(l1) + bsm[c4 * 4 + 2], 0.f);
            r.w = fmaxf(__uint_as_float(h1) + bsm[c4 * 4 + 3], 0.f);
            *(float4*)(op + c4 * 4) = r;
        }
    }
}

// ---------------- launch ----------------
extern "C" void kernel_launch(void* const* d_in, const int* in_sizes, int n_in,
                              void* d_out, int out_size) {
    const float* x     = (const float*)d_in[0];
    const float* lvals = (const float*)d_in[1];
    const float* wk    = (const float*)d_in[2];
    const float* bias  = (const float*)d_in[3];
    const int*   rows  = (const int*)d_in[4];
    const int*   cols  = (const int*)d_in[5];
    float* out = (float*)d_out;

    float *t1, *t2, *t3;
    cudaGetSymbolAddress((void**)&t1, d_T1);
    cudaGetSymbolAddress((void**)&t2, d_T2);
    cudaGetSymbolAddress((void**)&t3, d_T3);

    // launch 1: bucket build (d_cnt zero from load-time init / previous gemm)
    scatter_k<<<(EN / 4 + 255) / 256, 256>>>(lvals, rows, cols);

    // launches 2-4: Chebyshev recurrence (spmm3 = #4 -> profiled)
    spmm_k<1, 0, 0><<<(MN + 7) / 8, 256>>>(x,  nullptr, t1, 1.0f);  // T1 = L x
    spmm_k<0, 1, 1><<<(MN + 7) / 8, 256>>>(t1, x,       t2, 2.0f);  // T2 = 2 L T1 - x
    spmm_k<0, 1, 0><<<(MN + 7) / 8, 256>>>(t2, t1,      t3, 2.0f);  // T3 = 2 L T2 - T1

    // launch 5: cp.async-pipelined projection + bias + relu + d_cnt re-zero
    gemm_k<<<(NB * MN + GTHR - 1) / GTHR, GTHR>>>(x, t1, t2, t3, wk, bias, out);
}